// round 5
// baseline (speedup 1.0000x reference)
#include <cuda_runtime.h>
#include <cuda_fp16.h>
#include <stdint.h>

#define T_TOK 2048
#define KDIM  2048
#define IDIM  1024
#define NEXP  8
#define NJOBS 9
#define CAP   4096
#define TOPK  2

// ---------------- scratch (device globals) ----------------
__device__ int   g_cnt[NJOBS];
__device__ int   g_tok[NJOBS * CAP];
__device__ float g_prob[NJOBS * CAP];
__device__ __align__(16) __half g_xh[(size_t)T_TOK * KDIM];                 // [t][k]
__device__ __align__(16) __half g_wgu[(size_t)NJOBS * KDIM * 2 * IDIM];     // [job][k][2I]
__device__ __align__(16) __half g_wd [(size_t)NJOBS * IDIM * KDIM];         // [job][i][K]
__device__ __align__(16) __half g_acth[(size_t)NJOBS * CAP * IDIM];         // [job][slot][i]

// ---------------- fp4 dequant ----------------
__device__ __forceinline__ float fp4_val(unsigned nib, float half_scale) {
    unsigned mag = (0xC8643210u >> ((nib & 7u) * 4)) & 0xFu;
    float f = (float)mag;
    f = __int_as_float(__float_as_int(f) | ((nib & 8u) << 28));
    return f * half_scale;
}

// ---------------- mma helpers ----------------
__device__ __forceinline__ uint32_t sptr(const void* p) {
    return (uint32_t)__cvta_generic_to_shared(p);
}

__device__ __forceinline__ void ldsm4(uint32_t* r, uint32_t a) {
    asm volatile("ldmatrix.sync.aligned.m8n8.x4.shared.b16 {%0,%1,%2,%3}, [%4];"
        : "=r"(r[0]), "=r"(r[1]), "=r"(r[2]), "=r"(r[3]) : "r"(a));
}

__device__ __forceinline__ void ldsm4t(uint32_t* r, uint32_t a) {
    asm volatile("ldmatrix.sync.aligned.m8n8.x4.trans.shared.b16 {%0,%1,%2,%3}, [%4];"
        : "=r"(r[0]), "=r"(r[1]), "=r"(r[2]), "=r"(r[3]) : "r"(a));
}

__device__ __forceinline__ void mma16816(float* d, const uint32_t* a, uint32_t b0, uint32_t b1) {
    asm volatile("mma.sync.aligned.m16n8k16.row.col.f32.f16.f16.f32 "
        "{%0,%1,%2,%3},{%4,%5,%6,%7},{%8,%9},{%0,%1,%2,%3};"
        : "+f"(d[0]), "+f"(d[1]), "+f"(d[2]), "+f"(d[3])
        : "r"(a[0]), "r"(a[1]), "r"(a[2]), "r"(a[3]), "r"(b0), "r"(b1));
}

// ---------------- kernel 0: zero out + counters ----------------
__global__ void k_zero(float* __restrict__ out) {
    int i = blockIdx.x * 256 + threadIdx.x;
    out[i] = 0.0f;
    if (blockIdx.x == 0 && threadIdx.x < NJOBS) g_cnt[threadIdx.x] = 0;
}

// ---------------- kernel 1: routing ----------------
__global__ void k_route(const int* __restrict__ ids, const float* __restrict__ probs) {
    int t = blockIdx.x * 256 + threadIdx.x;
    for (int s = 0; s < TOPK; s++) {
        int e   = ids[t * TOPK + s];
        float p = probs[t * TOPK + s];
        int pos = atomicAdd(&g_cnt[e], 1);
        g_tok[e * CAP + pos]  = t;
        g_prob[e * CAP + pos] = p;
    }
    g_tok[NEXP * CAP + t]  = t;
    g_prob[NEXP * CAP + t] = 1.0f;
    if (t == 0) g_cnt[NEXP] = T_TOK;
}

// ---------------- kernel 2: x -> fp16 ----------------
__global__ void k_x2h(const float* __restrict__ x) {
    int i = blockIdx.x * 256 + threadIdx.x;
    g_xh[i] = __float2half_rn(x[i]);
}

// ---------------- kernel 3: dequant, coalesced k-major output ----------------
// Wq: [Kd/8][Nd] int32, S: [Kd/64][Nd]. Out: [Kd][Nd] fp16 (k-major).
// Tile: 256 k-rows x 64 n-cols per block.
__global__ __launch_bounds__(256) void k_dq(
    const int* __restrict__ Wq, const float* __restrict__ S,
    const int* __restrict__ Wqs, const float* __restrict__ Ss,
    __half* __restrict__ Out, int Kd, int Nd)
{
    __shared__ int   wsm[32][65];
    __shared__ float ssm[4][64];

    const int job = blockIdx.z;
    const int* W; const float* Sc;
    if (job < NEXP) {
        W  = Wq + (size_t)job * (Kd >> 3) * Nd;
        Sc = S  + (size_t)job * (Kd >> 6) * Nd;
    } else { W = Wqs; Sc = Ss; }
    __half* O = Out + (size_t)job * Kd * Nd;

    const int n0  = blockIdx.x * 64;
    const int kw0 = blockIdx.y * 32;
    const int tid = threadIdx.x;

    for (int i = 0; i < 8; i++) {
        int o = tid + i * 256;
        int r = o >> 6, cn = o & 63;
        wsm[r][cn] = W[(size_t)(kw0 + r) * Nd + n0 + cn];
    }
    {
        int g = tid >> 6, cn = tid & 63;
        ssm[g][cn] = Sc[(size_t)((kw0 >> 3) + g) * Nd + n0 + cn] * 0.5f;
    }
    __syncthreads();

    for (int i = 0; i < 8; i++) {
        int idx  = tid + i * 256;
        int krow = idx >> 3;          // 0..255
        int seg  = idx & 7;           // 16B segment (8 n-cols)
        int kw   = krow >> 3;
        int nib  = (krow & 7) * 4;
        int grp  = krow >> 6;
        unsigned pk[4];
        for (int j = 0; j < 4; j++) {
            int c0 = seg * 8 + j * 2;
            float v0 = fp4_val((unsigned)(wsm[kw][c0]     >> nib) & 0xFu, ssm[grp][c0]);
            float v1 = fp4_val((unsigned)(wsm[kw][c0 + 1] >> nib) & 0xFu, ssm[grp][c0 + 1]);
            __half2 h2 = __floats2half2_rn(v0, v1);
            pk[j] = *reinterpret_cast<unsigned*>(&h2);
        }
        *(uint4*)(O + (size_t)(kw0 * 8 + krow) * Nd + n0 + seg * 8) =
            make_uint4(pk[0], pk[1], pk[2], pk[3]);
    }
}

// ---------------- kernel 4: gate_up HMMA GEMM + silu ----------------
// 128 threads = 4 warps, each warp 32 rows x 64 cols. Tile: 128 tok x
// (32 gate + 32 up) cols, BK=32. Register-prefetch pipelined.
__global__ __launch_bounds__(128) void k_gemm1() {
    __shared__ __align__(16) __half As[128 * 40];
    __shared__ __align__(16) __half Bs[32 * 72];
    __shared__ int ts[128];

    const int job  = blockIdx.z;
    const int cnt  = g_cnt[job];
    const int base = blockIdx.x * 128;
    if (base >= cnt) return;

    const int n0   = blockIdx.y * 32;       // i-base (32 i-cols per block)
    const int tid  = threadIdx.x;
    const int lane = tid & 31;
    const int warp = tid >> 5;
    const int wm   = warp * 32;
    const __half* Wb = g_wgu + (size_t)job * KDIM * (2 * IDIM);

    {
        int p = base + tid;
        ts[tid] = (p < cnt) ? g_tok[job * CAP + p] : 0;
    }
    __syncthreads();

    // A fill: 4 chunks/thread (128 rows x 32 k)
    int atok[4];
    int aoff[4];
    for (int i = 0; i < 4; i++) {
        int o   = tid + i * 128;
        int row = o >> 2;
        aoff[i] = row * 40 + (o & 3) * 8;
        atok[i] = ts[row];
    }
    // B fill: 2 chunks/thread (32 k-rows x 64 cols: 32 gate | 32 up)
    int bso[2];
    int bgc[2];
    int bkr[2];
    for (int i = 0; i < 2; i++) {
        int o   = tid + i * 128;
        int row = o >> 3;
        int ch  = o & 7;
        bkr[i]  = row;
        bso[i]  = row * 72 + ch * 8;
        bgc[i]  = (ch < 4) ? (n0 + ch * 8) : (IDIM + n0 + (ch - 4) * 8);
    }

    const uint32_t a_base = sptr(As) + ((wm + (lane & 15)) * 40 + (lane >> 4) * 8) * 2;
    const uint32_t b_base = sptr(Bs) + ((lane & 15) * 72 + (lane >> 4) * 8) * 2;

    float acc[2][8][4];
    for (int i = 0; i < 2; i++)
        for (int j = 0; j < 8; j++)
            for (int k = 0; k < 4; k++) acc[i][j][k] = 0.f;

    uint4 pa[4];
    uint4 pb[2];
    for (int i = 0; i < 4; i++)
        pa[i] = *(const uint4*)(g_xh + (size_t)atok[i] * KDIM + (aoff[i] % 40 - 0) * 0 + ((tid + i * 128) & 3) * 8);
    // (recompute cleanly below)
    for (int i = 0; i < 4; i++) {
        int o = tid + i * 128;
        pa[i] = *(const uint4*)(g_xh + (size_t)atok[i] * KDIM + (o & 3) * 8);
    }
    for (int i = 0; i < 2; i++)
        pb[i] = *(const uint4*)(Wb + (size_t)bkr[i] * (2 * IDIM) + bgc[i]);

    const int C = KDIM / 32;
    for (int c = 0; c < C; c++) {
        for (int i = 0; i < 4; i++) *(uint4*)&As[aoff[i]] = pa[i];
        for (int i = 0; i < 2; i++) *(uint4*)&Bs[bso[i]]  = pb[i];
        __syncthreads();

        if (c + 1 < C) {
            int kc = (c + 1) * 32;
            for (int i = 0; i < 4; i++) {
                int o = tid + i * 128;
                pa[i] = *(const uint4*)(g_xh + (size_t)atok[i] * KDIM + kc + (o & 3) * 8);
            }
            for (int i = 0; i < 2; i++)
                pb[i] = *(const uint4*)(Wb + (size_t)(kc + bkr[i]) * (2 * IDIM) + bgc[i]);
        }

        for (int ks = 0; ks < 2; ks++) {
            uint32_t a0[4];
            uint32_t a1[4];
            ldsm4(a0, a_base + ks * 32);
            ldsm4(a1, a_base + ks * 32 + 16 * 40 * 2);
            for (int jp = 0; jp < 4; jp++) {
                uint32_t b[4];
                ldsm4t(b, b_base + jp * 32 + ks * (16 * 72 * 2));
                mma16816(acc[0][jp * 2 + 0], a0, b[0], b[1]);
                mma16816(acc[1][jp * 2 + 0], a1, b[0], b[1]);
                mma16816(acc[0][jp * 2 + 1], a0, b[2], b[3]);
                mma16816(acc[1][jp * 2 + 1], a1, b[2], b[3]);
            }
        }
        __syncthreads();
    }

    // epilogue: jp 0..1 = gate blocks, jp+2 = matching up blocks
    __half* actb = g_acth + (size_t)job * CAP * IDIM;
    for (int am = 0; am < 2; am++) {
        for (int h = 0; h < 2; h++) {
            int r   = wm + am * 16 + (lane >> 2) + h * 8;
            int pos = base + r;
            if (pos >= cnt) continue;
            __half* orow = actb + (size_t)pos * IDIM;
            for (int jp = 0; jp < 2; jp++) {
                for (int jj = 0; jj < 2; jj++) {
                    float g0 = acc[am][jp * 2 + jj][h * 2 + 0];
                    float g1 = acc[am][jp * 2 + jj][h * 2 + 1];
                    float u0 = acc[am][(jp + 2) * 2 + jj][h * 2 + 0];
                    float u1 = acc[am][(jp + 2) * 2 + jj][h * 2 + 1];
                    float o0 = g0 / (1.0f + __expf(-g0)) * u0;
                    float o1 = g1 / (1.0f + __expf(-g1)) * u1;
                    int col = n0 + jp * 16 + jj * 8 + (lane & 3) * 2;
                    *(__half2*)(orow + col) = __floats2half2_rn(o0, o1);
                }
            }
        }
    }
}

// ---------------- kernel 5: down HMMA GEMM + weighted atomicAdd ----------------
// 128 threads, tile 128 slots x 64 K-cols, BK=32, prefetch pipelined.
__global__ __launch_bounds__(128) void k_gemm2(float* __restrict__ out) {
    __shared__ __align__(16) __half As[128 * 40];
    __shared__ __align__(16) __half Bs[32 * 72];
    __shared__ int   ts[128];
    __shared__ float ps[128];

    const int job  = blockIdx.z;
    const int cnt  = g_cnt[job];
    const int base = blockIdx.x * 128;
    if (base >= cnt) return;

    const int n0   = blockIdx.y * 64;       // output K-col base
    const int tid  = threadIdx.x;
    const int lane = tid & 31;
    const int warp = tid >> 5;
    const int wm   = warp * 32;
    const __half* Wb = g_wd + (size_t)job * IDIM * KDIM;
    const __half* Ab = g_acth + (size_t)job * CAP * IDIM;

    {
        int p  = base + tid;
        bool v = p < cnt;
        ts[tid] = v ? g_tok[job * CAP + p] : 0;
        ps[tid] = v ? g_prob[job * CAP + p] : 0.0f;
    }
    __syncthreads();

    int aoff[4];
    int arow[4];
    for (int i = 0; i < 4; i++) {
        int o   = tid + i * 128;
        arow[i] = o >> 2;
        aoff[i] = arow[i] * 40 + (o & 3) * 8;
    }
    int bso[2];
    int bkr[2];
    int bgc[2];
    for (int i = 0; i < 2; i++) {
        int o   = tid + i * 128;
        bkr[i]  = o >> 3;
        int ch  = o & 7;
        bso[i]  = bkr[i] * 72 + ch * 8;
        bgc[i]  = n0 + ch * 8;
    }

    const uint32_t a_base = sptr(As) + ((wm + (lane & 15)) * 40 + (lane >> 4) * 8) * 2;
    const uint32_t b_base = sptr(Bs) + ((lane & 15) * 72 + (lane >> 4) * 8) * 2;

    float acc[2][8][4];
    for (int i = 0; i < 2; i++)
        for (int j = 0; j < 8; j++)
            for (int k = 0; k < 4; k++) acc[i][j][k] = 0.f;

    uint4 pa[4];
    uint4 pb[2];
    for (int i = 0; i < 4; i++) {
        int o = tid + i * 128;
        pa[i] = *(const uint4*)(Ab + (size_t)(base + arow[i]) * IDIM + (o & 3) * 8);
    }
    for (int i = 0; i < 2; i++)
        pb[i] = *(const uint4*)(Wb + (size_t)bkr[i] * KDIM + bgc[i]);

    const int C = IDIM / 32;
    for (int c = 0; c < C; c++) {
        for (int i = 0; i < 4; i++) *(uint4*)&As[aoff[i]] = pa[i];
        for (int i = 0; i < 2; i++) *(uint4*)&Bs[bso[i]]  = pb[i];
        __syncthreads();

        if (c + 1 < C) {
            int kc = (c + 1) * 32;
            for (int i = 0; i < 4; i++) {
                int o = tid + i * 128;
                pa[i] = *(const uint4*)(Ab + (size_t)(base + arow[i]) * IDIM + kc + (o & 3) * 8);
            }
            for (int i = 0; i < 2; i++)
                pb[i] = *(const uint4*)(Wb + (size_t)(kc + bkr[i]) * KDIM + bgc[i]);
        }

        for (int ks = 0; ks < 2; ks++) {
            uint32_t a0[4];
            uint32_t a1[4];
            ldsm4(a0, a_base + ks * 32);
            ldsm4(a1, a_base + ks * 32 + 16 * 40 * 2);
            for (int jp = 0; jp < 4; jp++) {
                uint32_t b[4];
                ldsm4t(b, b_base + jp * 32 + ks * (16 * 72 * 2));
                mma16816(acc[0][jp * 2 + 0], a0, b[0], b[1]);
                mma16816(acc[1][jp * 2 + 0], a1, b[0], b[1]);
                mma16816(acc[0][jp * 2 + 1], a0, b[2], b[3]);
                mma16816(acc[1][jp * 2 + 1], a1, b[2], b[3]);
            }
        }
        __syncthreads();
    }

    for (int am = 0; am < 2; am++) {
        for (int h = 0; h < 2; h++) {
            int r   = wm + am * 16 + (lane >> 2) + h * 8;
            int pos = base + r;
            if (pos >= cnt) continue;
            int   t = ts[r];
            float p = ps[r];
            float* ob = out + (size_t)t * KDIM;
            for (int j = 0; j < 8; j++) {
                int col = n0 + j * 8 + (lane & 3) * 2;
                atomicAdd(ob + col,     acc[am][j][h * 2 + 0] * p);
                atomicAdd(ob + col + 1, acc[am][j][h * 2 + 1] * p);
            }
        }
    }
}

// ---------------- launcher ----------------
extern "C" void kernel_launch(void* const* d_in, const int* in_sizes, int n_in,
                              void* d_out, int out_size) {
    const float* x     = (const float*)d_in[0];
    const int*   gup   = (const int*)  d_in[1];
    const float* gus   = (const float*)d_in[2];
    const int*   dwp   = (const int*)  d_in[3];
    const float* dws   = (const float*)d_in[4];
    const int*   sgup  = (const int*)  d_in[5];
    const float* sgus  = (const float*)d_in[6];
    const int*   sdp   = (const int*)  d_in[7];
    const float* sds   = (const float*)d_in[8];
    const int*   ids   = (const int*)  d_in[9];
    const float* probs = (const float*)d_in[10];
    float* out = (float*)d_out;

    __half* wgu;
    __half* wd;
    cudaGetSymbolAddress((void**)&wgu, g_wgu);
    cudaGetSymbolAddress((void**)&wd,  g_wd);

    k_zero <<<(T_TOK * KDIM) / 256, 256>>>(out);
    k_route<<<T_TOK / 256, 256>>>(ids, probs);
    k_x2h  <<<(T_TOK * KDIM) / 256, 256>>>(x);
    // gate_up: Kd=2048, Nd=4096? no: Nd = 2*IDIM = 2048
    k_dq<<<dim3((2 * IDIM) / 64, KDIM / 256, NJOBS), 256>>>(gup, gus, sgup, sgus, wgu, KDIM, 2 * IDIM);
    // down: Kd=1024, Nd=2048
    k_dq<<<dim3(KDIM / 64, IDIM / 256, NJOBS), 256>>>(dwp, dws, sdp, sds, wd, IDIM, KDIM);
    k_gemm1<<<dim3(CAP / 128, IDIM / 32, NJOBS), 128>>>();
    k_gemm2<<<dim3(CAP / 128, KDIM / 64, NJOBS), 128>>>(out);
}

// round 6
// speedup vs baseline: 1.1771x; 1.1771x over previous
#include <cuda_runtime.h>
#include <cuda_fp16.h>
#include <stdint.h>

#define T_TOK 2048
#define KDIM  2048
#define IDIM  1024
#define NEXP  8
#define NJOBS 9
#define CAP   4096
#define TOPK  2

// ---------------- scratch (device globals) ----------------
__device__ int   g_cnt[NJOBS];
__device__ int   g_tok[NJOBS * CAP];
__device__ float g_prob[NJOBS * CAP];
__device__ __align__(16) __half g_xh[(size_t)T_TOK * KDIM];                 // [t][k]
__device__ __align__(16) __half g_wgu[(size_t)NJOBS * KDIM * 2 * IDIM];     // [job][k][2I]
__device__ __align__(16) __half g_wd [(size_t)NJOBS * IDIM * KDIM];         // [job][i][K]
__device__ __align__(16) __half g_acth[(size_t)NJOBS * CAP * IDIM];         // [job][slot][i]

// ---------------- fp4 dequant ----------------
__device__ __forceinline__ float fp4_val(unsigned nib, float half_scale) {
    unsigned mag = (0xC8643210u >> ((nib & 7u) * 4)) & 0xFu;
    float f = (float)mag;
    f = __int_as_float(__float_as_int(f) | ((nib & 8u) << 28));
    return f * half_scale;
}

// ---------------- helpers ----------------
__device__ __forceinline__ uint32_t sptr(const void* p) {
    return (uint32_t)__cvta_generic_to_shared(p);
}
__device__ __forceinline__ void cp16(uint32_t dst, const void* src) {
    asm volatile("cp.async.cg.shared.global [%0], [%1], 16;" :: "r"(dst), "l"(src));
}
__device__ __forceinline__ void cpcommit() { asm volatile("cp.async.commit_group;"); }
__device__ __forceinline__ void cpwait1()  { asm volatile("cp.async.wait_group 1;"); }
__device__ __forceinline__ void cpwait0()  { asm volatile("cp.async.wait_group 0;"); }

__device__ __forceinline__ void ldsm4(uint32_t* r, uint32_t a) {
    asm volatile("ldmatrix.sync.aligned.m8n8.x4.shared.b16 {%0,%1,%2,%3}, [%4];"
        : "=r"(r[0]), "=r"(r[1]), "=r"(r[2]), "=r"(r[3]) : "r"(a));
}
__device__ __forceinline__ void ldsm4t(uint32_t* r, uint32_t a) {
    asm volatile("ldmatrix.sync.aligned.m8n8.x4.trans.shared.b16 {%0,%1,%2,%3}, [%4];"
        : "=r"(r[0]), "=r"(r[1]), "=r"(r[2]), "=r"(r[3]) : "r"(a));
}
__device__ __forceinline__ void mma16816(float* d, const uint32_t* a, uint32_t b0, uint32_t b1) {
    asm volatile("mma.sync.aligned.m16n8k16.row.col.f32.f16.f16.f32 "
        "{%0,%1,%2,%3},{%4,%5,%6,%7},{%8,%9},{%0,%1,%2,%3};"
        : "+f"(d[0]), "+f"(d[1]), "+f"(d[2]), "+f"(d[3])
        : "r"(a[0]), "r"(a[1]), "r"(a[2]), "r"(a[3]), "r"(b0), "r"(b1));
}

#define A_STRIDE 40
#define B_STRIDE 136

// ---------------- kernel 0: zero out + counters ----------------
__global__ void k_zero(float* __restrict__ out) {
    int i = blockIdx.x * 256 + threadIdx.x;
    out[i] = 0.0f;
    if (blockIdx.x == 0 && threadIdx.x < NJOBS) g_cnt[threadIdx.x] = 0;
}

// ---------------- kernel 1: routing ----------------
__global__ void k_route(const int* __restrict__ ids, const float* __restrict__ probs) {
    int t = blockIdx.x * 256 + threadIdx.x;
    for (int s = 0; s < TOPK; s++) {
        int e   = ids[t * TOPK + s];
        float p = probs[t * TOPK + s];
        int pos = atomicAdd(&g_cnt[e], 1);
        g_tok[e * CAP + pos]  = t;
        g_prob[e * CAP + pos] = p;
    }
    g_tok[NEXP * CAP + t]  = t;
    g_prob[NEXP * CAP + t] = 1.0f;
    if (t == 0) g_cnt[NEXP] = T_TOK;
}

// ---------------- kernel 2: x -> fp16 ----------------
__global__ void k_x2h(const float* __restrict__ x) {
    int i = blockIdx.x * 256 + threadIdx.x;
    g_xh[i] = __float2half_rn(x[i]);
}

// ---------------- kernel 3: dequant, coalesced k-major output ----------------
__global__ __launch_bounds__(256) void k_dq(
    const int* __restrict__ Wq, const float* __restrict__ S,
    const int* __restrict__ Wqs, const float* __restrict__ Ss,
    __half* __restrict__ Out, int Kd, int Nd)
{
    __shared__ int   wsm[32][65];
    __shared__ float ssm[4][64];

    const int job = blockIdx.z;
    const int* W; const float* Sc;
    if (job < NEXP) {
        W  = Wq + (size_t)job * (Kd >> 3) * Nd;
        Sc = S  + (size_t)job * (Kd >> 6) * Nd;
    } else { W = Wqs; Sc = Ss; }
    __half* O = Out + (size_t)job * Kd * Nd;

    const int n0  = blockIdx.x * 64;
    const int kw0 = blockIdx.y * 32;
    const int tid = threadIdx.x;

    for (int i = 0; i < 8; i++) {
        int o = tid + i * 256;
        int r = o >> 6, cn = o & 63;
        wsm[r][cn] = W[(size_t)(kw0 + r) * Nd + n0 + cn];
    }
    {
        int g = tid >> 6, cn = tid & 63;
        ssm[g][cn] = Sc[(size_t)((kw0 >> 3) + g) * Nd + n0 + cn] * 0.5f;
    }
    __syncthreads();

    for (int i = 0; i < 8; i++) {
        int idx  = tid + i * 256;
        int krow = idx >> 3;
        int seg  = idx & 7;
        int kw   = krow >> 3;
        int nib  = (krow & 7) * 4;
        int grp  = krow >> 6;
        unsigned pk[4];
        for (int j = 0; j < 4; j++) {
            int c0 = seg * 8 + j * 2;
            float v0 = fp4_val((unsigned)(wsm[kw][c0]     >> nib) & 0xFu, ssm[grp][c0]);
            float v1 = fp4_val((unsigned)(wsm[kw][c0 + 1] >> nib) & 0xFu, ssm[grp][c0 + 1]);
            __half2 h2 = __floats2half2_rn(v0, v1);
            pk[j] = *reinterpret_cast<unsigned*>(&h2);
        }
        *(uint4*)(O + (size_t)(kw0 * 8 + krow) * Nd + n0 + seg * 8) =
            make_uint4(pk[0], pk[1], pk[2], pk[3]);
    }
}

// ---------------- kernel 4: gate_up HMMA GEMM + silu ----------------
// 256 threads = 8 warps (4m x 2n). Tile M=128, N=128 (per-warp 32 gate + 32 up
// interleaved), BK=32, cp.async double buffer.
__global__ __launch_bounds__(256) void k_gemm1() {
    __shared__ __align__(16) __half As[2][128 * A_STRIDE];
    __shared__ __align__(16) __half Bs[2][32 * B_STRIDE];
    __shared__ int ts[128];

    const int job  = blockIdx.z;
    const int cnt  = g_cnt[job];
    const int base = blockIdx.x * 128;
    if (base >= cnt) return;

    const int n0   = blockIdx.y * 64;        // 64 i-cols per block
    const int tid  = threadIdx.x;
    const int lane = tid & 31;
    const int warp = tid >> 5;
    const int wm   = (warp >> 1) * 32;
    const int wn   = (warp & 1) * 64;
    const int pair = warp & 1;               // which 32-i sub-range this warp owns
    const __half* Wb = g_xh;  // placeholder silence
    const __half* Wj = g_wgu + (size_t)job * KDIM * (2 * IDIM);

    if (tid < 128) {
        int p = base + tid;
        ts[tid] = (p < cnt) ? g_tok[job * CAP + p] : 0;
    }
    __syncthreads();

    // A fill: 512 16B chunks (128 rows x 4 segs), 2 per thread
    int arow[2], aseg[2], atok[2], aoff[2];
    for (int i = 0; i < 2; i++) {
        int c   = tid + i * 256;
        arow[i] = c >> 2;
        aseg[i] = c & 3;
        atok[i] = ts[arow[i]];
        aoff[i] = (arow[i] * A_STRIDE + aseg[i] * 8) * 2;
    }
    // B fill: 512 16B chunks (32 k-rows x 16 segs), 2 per thread
    // tile col c: p2 = seg>>3 (i-block), sub = (seg&7)*8; sub<32 gate else up
    int bkr[2], boff[2], bgc[2];
    for (int i = 0; i < 2; i++) {
        int c   = tid + i * 256;
        bkr[i]  = c >> 4;
        int seg = c & 15;
        boff[i] = (bkr[i] * B_STRIDE + seg * 8) * 2;
        int p2  = seg >> 3;
        int sub = (seg & 7) * 8;
        bgc[i]  = (sub < 32) ? (n0 + p2 * 32 + sub)
                             : (IDIM + n0 + p2 * 32 + (sub - 32));
    }

    const uint32_t asb = sptr(&As[0][0]);
    const uint32_t bsb = sptr(&Bs[0][0]);
    const uint32_t abufsz = 128 * A_STRIDE * 2;
    const uint32_t bbufsz = 32 * B_STRIDE * 2;
    const uint32_t a_frag = asb + ((wm + (lane & 15)) * A_STRIDE + (lane >> 4) * 8) * 2;
    const uint32_t b_frag = bsb + ((lane & 15) * B_STRIDE + wn + (lane >> 4) * 8) * 2;

    float acc[2][8][4];
    for (int i = 0; i < 2; i++)
        for (int j = 0; j < 8; j++)
            for (int k = 0; k < 4; k++) acc[i][j][k] = 0.f;

    auto fill = [&](int c, int buf) {
        int kc = c * 32;
        for (int i = 0; i < 2; i++)
            cp16(asb + buf * abufsz + aoff[i],
                 g_xh + (size_t)atok[i] * KDIM + kc + aseg[i] * 8);
        for (int i = 0; i < 2; i++)
            cp16(bsb + buf * bbufsz + boff[i],
                 Wj + (size_t)(kc + bkr[i]) * (2 * IDIM) + bgc[i]);
        cpcommit();
    };

    fill(0, 0);
    fill(1, 1);

    const int C = KDIM / 32;
    for (int c = 0; c < C; c++) {
        if (c == C - 1) cpwait0(); else cpwait1();
        __syncthreads();
        int buf = c & 1;
        uint32_t ab = a_frag + buf * abufsz;
        uint32_t bb = b_frag + buf * bbufsz;
        for (int ks = 0; ks < 2; ks++) {
            uint32_t a0[4], a1[4];
            ldsm4(a0, ab + ks * 32);
            ldsm4(a1, ab + ks * 32 + 16 * A_STRIDE * 2);
            for (int jp = 0; jp < 4; jp++) {
                uint32_t b[4];
                ldsm4t(b, bb + jp * 32 + ks * (16 * B_STRIDE * 2));
                mma16816(acc[0][jp * 2 + 0], a0, b[0], b[1]);
                mma16816(acc[1][jp * 2 + 0], a1, b[0], b[1]);
                mma16816(acc[0][jp * 2 + 1], a0, b[2], b[3]);
                mma16816(acc[1][jp * 2 + 1], a1, b[2], b[3]);
            }
        }
        __syncthreads();
        if (c + 2 < C) fill(c + 2, buf);
    }

    // epilogue: warp frags jp 0-1 = gate (cols 0-31 of warp), jp 2-3 = up
    __half* actb = g_acth + (size_t)job * CAP * IDIM;
    for (int am = 0; am < 2; am++) {
        for (int h = 0; h < 2; h++) {
            int r   = wm + am * 16 + (lane >> 2) + h * 8;
            int pos = base + r;
            if (pos >= cnt) continue;
            __half* orow = actb + (size_t)pos * IDIM;
            for (int jp = 0; jp < 2; jp++) {
                for (int jj = 0; jj < 2; jj++) {
                    float g0 = acc[am][jp * 2 + jj][h * 2 + 0];
                    float g1 = acc[am][jp * 2 + jj][h * 2 + 1];
                    float u0 = acc[am][(jp + 2) * 2 + jj][h * 2 + 0];
                    float u1 = acc[am][(jp + 2) * 2 + jj][h * 2 + 1];
                    float o0 = g0 / (1.0f + __expf(-g0)) * u0;
                    float o1 = g1 / (1.0f + __expf(-g1)) * u1;
                    int col = n0 + pair * 32 + jp * 16 + jj * 8 + (lane & 3) * 2;
                    *(__half2*)(orow + col) = __floats2half2_rn(o0, o1);
                }
            }
        }
    }
    (void)Wb;
}

// ---------------- kernel 5: down HMMA GEMM + weighted atomicAdd ----------------
// Tile M=128 slots x N=128 K-cols, BK=32, cp.async double buffer.
__global__ __launch_bounds__(256) void k_gemm2(float* __restrict__ out) {
    __shared__ __align__(16) __half As[2][128 * A_STRIDE];
    __shared__ __align__(16) __half Bs[2][32 * B_STRIDE];
    __shared__ int   ts[128];
    __shared__ float ps[128];

    const int job  = blockIdx.z;
    const int cnt  = g_cnt[job];
    const int base = blockIdx.x * 128;
    if (base >= cnt) return;

    const int n0   = blockIdx.y * 128;
    const int tid  = threadIdx.x;
    const int lane = tid & 31;
    const int warp = tid >> 5;
    const int wm   = (warp >> 1) * 32;
    const int wn   = (warp & 1) * 64;
    const __half* Wj = g_wd + (size_t)job * IDIM * KDIM;
    const __half* Ab = g_acth + (size_t)job * CAP * IDIM;

    if (tid < 128) {
        int p  = base + tid;
        bool v = p < cnt;
        ts[tid] = v ? g_tok[job * CAP + p] : 0;
        ps[tid] = v ? g_prob[job * CAP + p] : 0.0f;
    }
    __syncthreads();

    int arow[2], aseg[2], aoff[2];
    for (int i = 0; i < 2; i++) {
        int c   = tid + i * 256;
        arow[i] = c >> 2;
        aseg[i] = c & 3;
        aoff[i] = (arow[i] * A_STRIDE + aseg[i] * 8) * 2;
    }
    int bkr[2], boff[2], bgc[2];
    for (int i = 0; i < 2; i++) {
        int c   = tid + i * 256;
        bkr[i]  = c >> 4;
        int seg = c & 15;
        boff[i] = (bkr[i] * B_STRIDE + seg * 8) * 2;
        bgc[i]  = n0 + seg * 8;
    }

    const uint32_t asb = sptr(&As[0][0]);
    const uint32_t bsb = sptr(&Bs[0][0]);
    const uint32_t abufsz = 128 * A_STRIDE * 2;
    const uint32_t bbufsz = 32 * B_STRIDE * 2;
    const uint32_t a_frag = asb + ((wm + (lane & 15)) * A_STRIDE + (lane >> 4) * 8) * 2;
    const uint32_t b_frag = bsb + ((lane & 15) * B_STRIDE + wn + (lane >> 4) * 8) * 2;

    float acc[2][8][4];
    for (int i = 0; i < 2; i++)
        for (int j = 0; j < 8; j++)
            for (int k = 0; k < 4; k++) acc[i][j][k] = 0.f;

    auto fill = [&](int c, int buf) {
        int kc = c * 32;
        for (int i = 0; i < 2; i++)
            cp16(asb + buf * abufsz + aoff[i],
                 Ab + (size_t)(base + arow[i]) * IDIM + kc + aseg[i] * 8);
        for (int i = 0; i < 2; i++)
            cp16(bsb + buf * bbufsz + boff[i],
                 Wj + (size_t)(kc + bkr[i]) * KDIM + bgc[i]);
        cpcommit();
    };

    fill(0, 0);
    fill(1, 1);

    const int C = IDIM / 32;
    for (int c = 0; c < C; c++) {
        if (c == C - 1) cpwait0(); else cpwait1();
        __syncthreads();
        int buf = c & 1;
        uint32_t ab = a_frag + buf * abufsz;
        uint32_t bb = b_frag + buf * bbufsz;
        for (int ks = 0; ks < 2; ks++) {
            uint32_t a0[4], a1[4];
            ldsm4(a0, ab + ks * 32);
            ldsm4(a1, ab + ks * 32 + 16 * A_STRIDE * 2);
            for (int jp = 0; jp < 4; jp++) {
                uint32_t b[4];
                ldsm4t(b, bb + jp * 32 + ks * (16 * B_STRIDE * 2));
                mma16816(acc[0][jp * 2 + 0], a0, b[0], b[1]);
                mma16816(acc[1][jp * 2 + 0], a1, b[0], b[1]);
                mma16816(acc[0][jp * 2 + 1], a0, b[2], b[3]);
                mma16816(acc[1][jp * 2 + 1], a1, b[2], b[3]);
            }
        }
        __syncthreads();
        if (c + 2 < C) fill(c + 2, buf);
    }

    for (int am = 0; am < 2; am++) {
        for (int h = 0; h < 2; h++) {
            int r   = wm + am * 16 + (lane >> 2) + h * 8;
            int pos = base + r;
            if (pos >= cnt) continue;
            int   t = ts[r];
            float p = ps[r];
            float* ob = out + (size_t)t * KDIM;
            for (int j = 0; j < 8; j++) {
                int col = n0 + wn + (j >> 1) * 16 + (j & 1) * 8 + (lane & 3) * 2;
                atomicAdd(ob + col,     acc[am][j][h * 2 + 0] * p);
                atomicAdd(ob + col + 1, acc[am][j][h * 2 + 1] * p);
            }
        }
    }
}

// ---------------- launcher ----------------
extern "C" void kernel_launch(void* const* d_in, const int* in_sizes, int n_in,
                              void* d_out, int out_size) {
    const float* x     = (const float*)d_in[0];
    const int*   gup   = (const int*)  d_in[1];
    const float* gus   = (const float*)d_in[2];
    const int*   dwp   = (const int*)  d_in[3];
    const float* dws   = (const float*)d_in[4];
    const int*   sgup  = (const int*)  d_in[5];
    const float* sgus  = (const float*)d_in[6];
    const int*   sdp   = (const int*)  d_in[7];
    const float* sds   = (const float*)d_in[8];
    const int*   ids   = (const int*)  d_in[9];
    const float* probs = (const float*)d_in[10];
    float* out = (float*)d_out;

    __half* wgu;
    __half* wd;
    cudaGetSymbolAddress((void**)&wgu, g_wgu);
    cudaGetSymbolAddress((void**)&wd,  g_wd);

    k_zero <<<(T_TOK * KDIM) / 256, 256>>>(out);
    k_route<<<T_TOK / 256, 256>>>(ids, probs);
    k_x2h  <<<(T_TOK * KDIM) / 256, 256>>>(x);
    k_dq<<<dim3((2 * IDIM) / 64, KDIM / 256, NJOBS), 256>>>(gup, gus, sgup, sgus, wgu, KDIM, 2 * IDIM);
    k_dq<<<dim3(KDIM / 64, IDIM / 256, NJOBS), 256>>>(dwp, dws, sdp, sds, wd, IDIM, KDIM);
    k_gemm1<<<dim3(CAP / 128, IDIM / 64, NJOBS), 256>>>();
    k_gemm2<<<dim3(CAP / 128, KDIM / 128, NJOBS), 256>>>(out);
}

// round 7
// speedup vs baseline: 1.2162x; 1.0333x over previous
#include <cuda_runtime.h>
#include <cuda_fp16.h>
#include <stdint.h>

#define T_TOK 2048
#define KDIM  2048
#define IDIM  1024
#define NEXP  8
#define NJOBS 9
#define CAP   4096
#define TOPK  2

#define A_STRIDE 40
#define B_STRIDE 136
#define ABUF (128 * A_STRIDE * 2)          // 10240 B per stage
#define BBUF (32 * B_STRIDE * 2)           // 8704 B per stage
#define BOFF (3 * ABUF)                    // 30720
#define TSOFF (3 * ABUF + 3 * BBUF)        // 56832
#define DSMEM (TSOFF + 512)                // 57344

// ---------------- scratch (device globals) ----------------
__device__ int   g_cnt[NJOBS];
__device__ int   g_tok[NJOBS * CAP];
__device__ int   g_slot[T_TOK * TOPK];
__device__ __align__(16) __half g_xh[(size_t)T_TOK * KDIM];                 // [t][k]
__device__ __align__(16) __half g_wgu[(size_t)NJOBS * KDIM * 2 * IDIM];     // [job][k][2I]
__device__ __align__(16) __half g_wd [(size_t)NJOBS * IDIM * KDIM];         // [job][i][K]
__device__ __align__(16) __half g_acth[(size_t)NJOBS * CAP * IDIM];         // [job][slot][i]
__device__ __align__(16) float  g_y[(size_t)NJOBS * CAP * KDIM];            // [slot][k]

// ---------------- helpers ----------------
__device__ __forceinline__ uint32_t sptr(const void* p) {
    return (uint32_t)__cvta_generic_to_shared(p);
}
__device__ __forceinline__ void cp16(uint32_t dst, const void* src) {
    asm volatile("cp.async.cg.shared.global [%0], [%1], 16;" :: "r"(dst), "l"(src));
}
__device__ __forceinline__ void cpcommit() { asm volatile("cp.async.commit_group;"); }
__device__ __forceinline__ void cpwait1()  { asm volatile("cp.async.wait_group 1;"); }
__device__ __forceinline__ void cpwait0()  { asm volatile("cp.async.wait_group 0;"); }

__device__ __forceinline__ void ldsm4(uint32_t* r, uint32_t a) {
    asm volatile("ldmatrix.sync.aligned.m8n8.x4.shared.b16 {%0,%1,%2,%3}, [%4];"
        : "=r"(r[0]), "=r"(r[1]), "=r"(r[2]), "=r"(r[3]) : "r"(a));
}
__device__ __forceinline__ void ldsm4t(uint32_t* r, uint32_t a) {
    asm volatile("ldmatrix.sync.aligned.m8n8.x4.trans.shared.b16 {%0,%1,%2,%3}, [%4];"
        : "=r"(r[0]), "=r"(r[1]), "=r"(r[2]), "=r"(r[3]) : "r"(a));
}
__device__ __forceinline__ void mma16816(float* d, const uint32_t* a, uint32_t b0, uint32_t b1) {
    asm volatile("mma.sync.aligned.m16n8k16.row.col.f32.f16.f16.f32 "
        "{%0,%1,%2,%3},{%4,%5,%6,%7},{%8,%9},{%0,%1,%2,%3};"
        : "+f"(d[0]), "+f"(d[1]), "+f"(d[2]), "+f"(d[3])
        : "r"(a[0]), "r"(a[1]), "r"(a[2]), "r"(a[3]), "r"(b0), "r"(b1));
}

// FP4 e2m1 -> fp16 bit construction: bits = ((n&7)<<9)|((n&8)<<12) encodes
// value * 2^-14 exactly; multiply by scale*16384 in fp32.
__device__ __forceinline__ float fp4_bits(unsigned nib, float s14) {
    unsigned b = ((nib & 7u) << 9) | ((nib & 8u) << 12);
    return __half2float(__ushort_as_half((unsigned short)b)) * s14;
}

// ---------------- kernel: init counters ----------------
__global__ void k_init() {
    if (threadIdx.x < NJOBS) g_cnt[threadIdx.x] = 0;
}

// ---------------- kernel: routing ----------------
__global__ void k_route(const int* __restrict__ ids, const float* __restrict__ probs) {
    int t = blockIdx.x * 256 + threadIdx.x;
    for (int s = 0; s < TOPK; s++) {
        int e   = ids[t * TOPK + s];
        int pos = atomicAdd(&g_cnt[e], 1);
        int slot = e * CAP + pos;
        g_tok[slot] = t;
        g_slot[t * TOPK + s] = slot;
    }
    g_tok[NEXP * CAP + t] = t;
    if (t == 0) g_cnt[NEXP] = T_TOK;
}

// ---------------- kernel: x -> fp16 ----------------
__global__ void k_x2h(const float* __restrict__ x) {
    int i = blockIdx.x * 256 + threadIdx.x;
    g_xh[i] = __float2half_rn(x[i]);
}

// ---------------- kernel: dequant, coalesced k-major output ----------------
__global__ __launch_bounds__(256) void k_dq(
    const int* __restrict__ Wq, const float* __restrict__ S,
    const int* __restrict__ Wqs, const float* __restrict__ Ss,
    __half* __restrict__ Out, int Kd, int Nd)
{
    __shared__ int   wsm[32][65];
    __shared__ float ssm[4][64];

    const int job = blockIdx.z;
    const int* W; const float* Sc;
    if (job < NEXP) {
        W  = Wq + (size_t)job * (Kd >> 3) * Nd;
        Sc = S  + (size_t)job * (Kd >> 6) * Nd;
    } else { W = Wqs; Sc = Ss; }
    __half* O = Out + (size_t)job * Kd * Nd;

    const int n0  = blockIdx.x * 64;
    const int kw0 = blockIdx.y * 32;
    const int tid = threadIdx.x;

    for (int i = 0; i < 8; i++) {
        int o = tid + i * 256;
        int r = o >> 6, cn = o & 63;
        wsm[r][cn] = W[(size_t)(kw0 + r) * Nd + n0 + cn];
    }
    {
        int g = tid >> 6, cn = tid & 63;
        ssm[g][cn] = Sc[(size_t)((kw0 >> 3) + g) * Nd + n0 + cn] * 16384.0f;
    }
    __syncthreads();

    for (int i = 0; i < 8; i++) {
        int idx  = tid + i * 256;
        int krow = idx >> 3;
        int seg  = idx & 7;
        int kw   = krow >> 3;
        int nib  = (krow & 7) * 4;
        int grp  = krow >> 6;
        unsigned pk[4];
        for (int j = 0; j < 4; j++) {
            int c0 = seg * 8 + j * 2;
            float v0 = fp4_bits((unsigned)(wsm[kw][c0]     >> nib) & 0xFu, ssm[grp][c0]);
            float v1 = fp4_bits((unsigned)(wsm[kw][c0 + 1] >> nib) & 0xFu, ssm[grp][c0 + 1]);
            __half2 h2 = __floats2half2_rn(v0, v1);
            pk[j] = *reinterpret_cast<unsigned*>(&h2);
        }
        *(uint4*)(O + (size_t)(kw0 * 8 + krow) * Nd + n0 + seg * 8) =
            make_uint4(pk[0], pk[1], pk[2], pk[3]);
    }
}

// ---------------- kernel: gate_up HMMA GEMM + silu ----------------
// 256 threads = 8 warps (4m x 2n). M=128, N=128 (per-warp 32 gate + 32 up),
// BK=32, 3-stage cp.async, one barrier per chunk.
__global__ __launch_bounds__(256) void k_gemm1() {
    extern __shared__ __align__(16) char sm[];
    int* ts = (int*)(sm + TSOFF);

    const int job  = blockIdx.z;
    const int cnt  = g_cnt[job];
    const int base = blockIdx.x * 128;
    if (base >= cnt) return;

    const int n0   = blockIdx.y * 64;
    const int tid  = threadIdx.x;
    const int lane = tid & 31;
    const int warp = tid >> 5;
    const int wm   = (warp >> 1) * 32;
    const int wn   = (warp & 1) * 64;
    const int pair = warp & 1;
    const __half* Wj = g_wgu + (size_t)job * KDIM * (2 * IDIM);

    if (tid < 128) {
        int p = base + tid;
        ts[tid] = (p < cnt) ? g_tok[job * CAP + p] : 0;
    }
    __syncthreads();

    int arow[2], aseg[2], atok[2], aoff[2];
    for (int i = 0; i < 2; i++) {
        int c   = tid + i * 256;
        arow[i] = c >> 2;
        aseg[i] = c & 3;
        atok[i] = ts[arow[i]];
        aoff[i] = (arow[i] * A_STRIDE + aseg[i] * 8) * 2;
    }
    int bkr[2], boff[2], bgc[2];
    for (int i = 0; i < 2; i++) {
        int c   = tid + i * 256;
        bkr[i]  = c >> 4;
        int seg = c & 15;
        boff[i] = (bkr[i] * B_STRIDE + seg * 8) * 2;
        int p2  = seg >> 3;
        int sub = (seg & 7) * 8;
        bgc[i]  = (sub < 32) ? (n0 + p2 * 32 + sub)
                             : (IDIM + n0 + p2 * 32 + (sub - 32));
    }

    const uint32_t asb = sptr(sm);
    const uint32_t bsb = asb + BOFF;
    const uint32_t a_frag = asb + ((wm + (lane & 15)) * A_STRIDE + (lane >> 4) * 8) * 2;
    const uint32_t b_frag = bsb + ((lane & 15) * B_STRIDE + wn + (lane >> 4) * 8) * 2;

    float acc[2][8][4];
    for (int i = 0; i < 2; i++)
        for (int j = 0; j < 8; j++)
            for (int k = 0; k < 4; k++) acc[i][j][k] = 0.f;

    auto fill = [&](int c, int buf) {
        int kc = c * 32;
        for (int i = 0; i < 2; i++)
            cp16(asb + buf * ABUF + aoff[i],
                 g_xh + (size_t)atok[i] * KDIM + kc + aseg[i] * 8);
        for (int i = 0; i < 2; i++)
            cp16(bsb + buf * BBUF + boff[i],
                 Wj + (size_t)(kc + bkr[i]) * (2 * IDIM) + bgc[i]);
        cpcommit();
    };

    fill(0, 0);
    fill(1, 1);

    const int C = KDIM / 32;
    for (int c = 0; c < C; c++) {
        if (c >= C - 1) cpwait0(); else cpwait1();
        __syncthreads();
        if (c + 2 < C) fill(c + 2, (c + 2) % 3);
        int buf = c % 3;
        uint32_t ab = a_frag + buf * ABUF;
        uint32_t bb = b_frag + buf * BBUF;
        for (int ks = 0; ks < 2; ks++) {
            uint32_t a0[4], a1[4];
            ldsm4(a0, ab + ks * 32);
            ldsm4(a1, ab + ks * 32 + 16 * A_STRIDE * 2);
            for (int jp = 0; jp < 4; jp++) {
                uint32_t b[4];
                ldsm4t(b, bb + jp * 32 + ks * (16 * B_STRIDE * 2));
                mma16816(acc[0][jp * 2 + 0], a0, b[0], b[1]);
                mma16816(acc[1][jp * 2 + 0], a1, b[0], b[1]);
                mma16816(acc[0][jp * 2 + 1], a0, b[2], b[3]);
                mma16816(acc[1][jp * 2 + 1], a1, b[2], b[3]);
            }
        }
    }

    __half* actb = g_acth + (size_t)job * CAP * IDIM;
    for (int am = 0; am < 2; am++) {
        for (int h = 0; h < 2; h++) {
            int r   = wm + am * 16 + (lane >> 2) + h * 8;
            int pos = base + r;
            if (pos >= cnt) continue;
            __half* orow = actb + (size_t)pos * IDIM;
            for (int jp = 0; jp < 2; jp++) {
                for (int jj = 0; jj < 2; jj++) {
                    float g0 = acc[am][jp * 2 + jj][h * 2 + 0];
                    float g1 = acc[am][jp * 2 + jj][h * 2 + 1];
                    float u0 = acc[am][(jp + 2) * 2 + jj][h * 2 + 0];
                    float u1 = acc[am][(jp + 2) * 2 + jj][h * 2 + 1];
                    float o0 = g0 / (1.0f + __expf(-g0)) * u0;
                    float o1 = g1 / (1.0f + __expf(-g1)) * u1;
                    int col = n0 + pair * 32 + jp * 16 + jj * 8 + (lane & 3) * 2;
                    *(__half2*)(orow + col) = __floats2half2_rn(o0, o1);
                }
            }
        }
    }
}

// ---------------- kernel: down HMMA GEMM -> g_y (per-slot fp32) ----------------
__global__ __launch_bounds__(256) void k_gemm2() {
    extern __shared__ __align__(16) char sm[];

    const int job  = blockIdx.z;
    const int cnt  = g_cnt[job];
    const int base = blockIdx.x * 128;
    if (base >= cnt) return;

    const int n0   = blockIdx.y * 128;
    const int tid  = threadIdx.x;
    const int lane = tid & 31;
    const int warp = tid >> 5;
    const int wm   = (warp >> 1) * 32;
    const int wn   = (warp & 1) * 64;
    const __half* Wj = g_wd + (size_t)job * IDIM * KDIM;
    const __half* Ab = g_acth + (size_t)job * CAP * IDIM;

    int arow[2], aseg[2], aoff[2];
    for (int i = 0; i < 2; i++) {
        int c   = tid + i * 256;
        arow[i] = c >> 2;
        aseg[i] = c & 3;
        aoff[i] = (arow[i] * A_STRIDE + aseg[i] * 8) * 2;
    }
    int bkr[2], boff[2], bgc[2];
    for (int i = 0; i < 2; i++) {
        int c   = tid + i * 256;
        bkr[i]  = c >> 4;
        int seg = c & 15;
        boff[i] = (bkr[i] * B_STRIDE + seg * 8) * 2;
        bgc[i]  = n0 + seg * 8;
    }

    const uint32_t asb = sptr(sm);
    const uint32_t bsb = asb + BOFF;
    const uint32_t a_frag = asb + ((wm + (lane & 15)) * A_STRIDE + (lane >> 4) * 8) * 2;
    const uint32_t b_frag = bsb + ((lane & 15) * B_STRIDE + wn + (lane >> 4) * 8) * 2;

    float acc[2][8][4];
    for (int i = 0; i < 2; i++)
        for (int j = 0; j < 8; j++)
            for (int k = 0; k < 4; k++) acc[i][j][k] = 0.f;

    auto fill = [&](int c, int buf) {
        int kc = c * 32;
        for (int i = 0; i < 2; i++)
            cp16(asb + buf * ABUF + aoff[i],
                 Ab + (size_t)(base + arow[i]) * IDIM + kc + aseg[i] * 8);
        for (int i = 0; i < 2; i++)
            cp16(bsb + buf * BBUF + boff[i],
                 Wj + (size_t)(kc + bkr[i]) * KDIM + bgc[i]);
        cpcommit();
    };

    fill(0, 0);
    fill(1, 1);

    const int C = IDIM / 32;
    for (int c = 0; c < C; c++) {
        if (c >= C - 1) cpwait0(); else cpwait1();
        __syncthreads();
        if (c + 2 < C) fill(c + 2, (c + 2) % 3);
        int buf = c % 3;
        uint32_t ab = a_frag + buf * ABUF;
        uint32_t bb = b_frag + buf * BBUF;
        for (int ks = 0; ks < 2; ks++) {
            uint32_t a0[4], a1[4];
            ldsm4(a0, ab + ks * 32);
            ldsm4(a1, ab + ks * 32 + 16 * A_STRIDE * 2);
            for (int jp = 0; jp < 4; jp++) {
                uint32_t b[4];
                ldsm4t(b, bb + jp * 32 + ks * (16 * B_STRIDE * 2));
                mma16816(acc[0][jp * 2 + 0], a0, b[0], b[1]);
                mma16816(acc[1][jp * 2 + 0], a1, b[0], b[1]);
                mma16816(acc[0][jp * 2 + 1], a0, b[2], b[3]);
                mma16816(acc[1][jp * 2 + 1], a1, b[2], b[3]);
            }
        }
    }

    float* yb = g_y + (size_t)job * CAP * KDIM;
    for (int am = 0; am < 2; am++) {
        for (int h = 0; h < 2; h++) {
            int r   = wm + am * 16 + (lane >> 2) + h * 8;
            int pos = base + r;
            if (pos >= cnt) continue;
            float* orow = yb + (size_t)pos * KDIM;
            for (int j = 0; j < 8; j++) {
                int col = n0 + wn + (j >> 1) * 16 + (j & 1) * 8 + (lane & 3) * 2;
                *(float2*)(orow + col) =
                    make_float2(acc[am][j][h * 2 + 0], acc[am][j][h * 2 + 1]);
            }
        }
    }
}

// ---------------- kernel: combine routed + shared -> out ----------------
__global__ __launch_bounds__(256) void k_combine(float* __restrict__ out,
                                                 const float* __restrict__ probs) {
    const int t = blockIdx.x;
    const float4* y0 = (const float4*)(g_y + (size_t)g_slot[t * TOPK + 0] * KDIM);
    const float4* y1 = (const float4*)(g_y + (size_t)g_slot[t * TOPK + 1] * KDIM);
    const float4* ys = (const float4*)(g_y + (size_t)(NEXP * CAP + t) * KDIM);
    const float p0 = probs[t * TOPK + 0];
    const float p1 = probs[t * TOPK + 1];
    float4* o = (float4*)(out + (size_t)t * KDIM);
    for (int i = threadIdx.x; i < KDIM / 4; i += 256) {
        float4 a = y0[i], b = y1[i], s = ys[i];
        float4 r;
        r.x = p0 * a.x + p1 * b.x + s.x;
        r.y = p0 * a.y + p1 * b.y + s.y;
        r.z = p0 * a.z + p1 * b.z + s.z;
        r.w = p0 * a.w + p1 * b.w + s.w;
        o[i] = r;
    }
}

// ---------------- launcher ----------------
extern "C" void kernel_launch(void* const* d_in, const int* in_sizes, int n_in,
                              void* d_out, int out_size) {
    const float* x     = (const float*)d_in[0];
    const int*   gup   = (const int*)  d_in[1];
    const float* gus   = (const float*)d_in[2];
    const int*   dwp   = (const int*)  d_in[3];
    const float* dws   = (const float*)d_in[4];
    const int*   sgup  = (const int*)  d_in[5];
    const float* sgus  = (const float*)d_in[6];
    const int*   sdp   = (const int*)  d_in[7];
    const float* sds   = (const float*)d_in[8];
    const int*   ids   = (const int*)  d_in[9];
    const float* probs = (const float*)d_in[10];
    float* out = (float*)d_out;

    cudaFuncSetAttribute(k_gemm1, cudaFuncAttributeMaxDynamicSharedMemorySize, DSMEM);
    cudaFuncSetAttribute(k_gemm2, cudaFuncAttributeMaxDynamicSharedMemorySize, DSMEM);

    __half* wgu;
    __half* wd;
    cudaGetSymbolAddress((void**)&wgu, g_wgu);
    cudaGetSymbolAddress((void**)&wd,  g_wd);

    k_init <<<1, 32>>>();
    k_route<<<T_TOK / 256, 256>>>(ids, probs);
    k_x2h  <<<(T_TOK * KDIM) / 256, 256>>>(x);
    k_dq<<<dim3((2 * IDIM) / 64, KDIM / 256, NJOBS), 256>>>(gup, gus, sgup, sgus, wgu, KDIM, 2 * IDIM);
    k_dq<<<dim3(KDIM / 64, IDIM / 256, NJOBS), 256>>>(dwp, dws, sdp, sds, wd, IDIM, KDIM);
    k_gemm1<<<dim3(CAP / 128, IDIM / 64, NJOBS), 256, DSMEM>>>();
    k_gemm2<<<dim3(CAP / 128, KDIM / 128, NJOBS), 256, DSMEM>>>();
    k_combine<<<T_TOK, 256>>>(out, probs);
}